// round 1
// baseline (speedup 1.0000x reference)
#include <cuda_runtime.h>
#include <math.h>

#define H    2048
#define TSTEPS 1024
#define NCTA 147          // ceil(2048/14); <= SM count (152) so all co-resident
#define MAXC 14           // columns per CTA
#define NTH  256          // 8 warps

// dynamic smem: 2 matrices * MAXC cols * H floats + 64 floats for dot results
#define SMEM_W_FLOATS (2 * MAXC * H)
#define SMEM_BYTES ((SMEM_W_FLOATS + 64) * 4)

// ---------------- persistent device state ----------------
__device__ float g_Wt[3ull * H * H];   // transposed weights: g_Wt[g][j][k] = Wh_g[k][j]
__device__ float g_u[3][H];            // u_g = We @ Wg
__device__ float g_v[3][H];            // v_g = be @ Wg + b_g
__device__ float g_xs[TSTEPS];         // snake-ordered x
__device__ float g_h[2][H];            // double-buffered hidden state
__device__ int   g_flags[NCTA];        // per-CTA step counters

// ---------------- memory-order helpers ----------------
__device__ __forceinline__ int ld_relaxed(const int* p) {
    int v;
    asm volatile("ld.relaxed.gpu.global.b32 %0, [%1];" : "=r"(v) : "l"(p) : "memory");
    return v;
}
__device__ __forceinline__ void st_release(int* p, int v) {
    asm volatile("st.release.gpu.global.b32 [%0], %1;" :: "l"(p), "r"(v) : "memory");
}

// ---------------- init: snake order, zero h0 and flags ----------------
__global__ void init_kernel(const float* __restrict__ x) {
    int t = threadIdx.x;          // 0..1023
    int row = t >> 5;             // Lx = Ly = 32
    int c = t & 31;
    int oc = (row & 1) ? (31 - c) : c;
    g_xs[t] = x[(row << 5) + oc];
    if (t < NCTA) g_flags[t] = 0;
    g_h[0][t] = 0.0f;
    g_h[0][t + 1024] = 0.0f;
}

// ---------------- transpose Whr/Whz/Whn into g_Wt (column-major) ----------------
__global__ void transpose_kernel(const float* __restrict__ Whr,
                                 const float* __restrict__ Whz,
                                 const float* __restrict__ Whn) {
    __shared__ float tile[32][33];
    const float* src = (blockIdx.z == 0) ? Whr : (blockIdx.z == 1) ? Whz : Whn;
    float* dst = g_Wt + (size_t)blockIdx.z * H * H;
    int k0 = blockIdx.x * 32;     // row index of src (k)
    int j0 = blockIdx.y * 32;     // col index of src (j)
    #pragma unroll
    for (int i = 0; i < 32; i += 8)
        tile[threadIdx.y + i][threadIdx.x] =
            src[(size_t)(k0 + threadIdx.y + i) * H + j0 + threadIdx.x];
    __syncthreads();
    #pragma unroll
    for (int i = 0; i < 32; i += 8)
        dst[(size_t)(j0 + threadIdx.y + i) * H + k0 + threadIdx.x] =
            tile[threadIdx.x][threadIdx.y + i];
}

// ---------------- prep: u_g = We@Wg, v_g = be@Wg + b_g ----------------
__global__ void prep_kernel(const float* __restrict__ We, const float* __restrict__ be,
                            const float* __restrict__ Wir, const float* __restrict__ bir,
                            const float* __restrict__ Wiz, const float* __restrict__ biz,
                            const float* __restrict__ Win, const float* __restrict__ bin_) {
    int j = blockIdx.x * blockDim.x + threadIdx.x;   // 0..2047
    float u0 = 0, v0 = 0, u1 = 0, v1 = 0, u2 = 0, v2 = 0;
    for (int k = 0; k < H; k++) {
        float we = We[k];
        float b  = be[k];
        float w;
        w = Wir[(size_t)k * H + j]; u0 = fmaf(we, w, u0); v0 = fmaf(b, w, v0);
        w = Wiz[(size_t)k * H + j]; u1 = fmaf(we, w, u1); v1 = fmaf(b, w, v1);
        w = Win[(size_t)k * H + j]; u2 = fmaf(we, w, u2); v2 = fmaf(b, w, v2);
    }
    g_u[0][j] = u0; g_v[0][j] = v0 + bir[j];
    g_u[1][j] = u1; g_v[1][j] = v1 + biz[j];
    g_u[2][j] = u2; g_v[2][j] = v2 + bin_[j];
}

// ---------------- persistent recurrent kernel ----------------
extern __shared__ float smem[];

__global__ void __launch_bounds__(NTH, 1) gru_kernel(const float* __restrict__ bhn,
                                                     float* __restrict__ out) {
    const int cta = blockIdx.x;
    const int tid = threadIdx.x;
    const int warp = tid >> 5;
    const int lane = tid & 31;
    const int cb = cta * MAXC;
    const int nc = min(MAXC, H - cb);     // 14 for all but last CTA (4)

    float* sw   = smem;                   // [2][nc][H] resident Whr/Whz slices
    float* sdot = smem + SMEM_W_FLOATS;   // [3*nc] dot results

    // Preload Whr/Whz column slices into SMEM (coalesced float4)
    {
        const float4* s0 = (const float4*)(g_Wt + (size_t)cb * H);
        const float4* s1 = (const float4*)(g_Wt + (size_t)H * H + (size_t)cb * H);
        float4* d0 = (float4*)sw;
        float4* d1 = (float4*)(sw + (size_t)nc * H);
        int n4 = nc * H / 4;
        for (int i = tid; i < n4; i += NTH) { d0[i] = s0[i]; d1[i] = s1[i]; }
    }

    // Per-column epilogue constants (threads 0..nc-1)
    float ur = 0, vr = 0, uz = 0, vz = 0, un = 0, vn = 0, bh = 0;
    if (tid < nc) {
        int j = cb + tid;
        ur = g_u[0][j]; vr = g_v[0][j];
        uz = g_u[1][j]; vz = g_v[1][j];
        un = g_u[2][j]; vn = g_v[2][j];
        bh = bhn[j];
    }
    __syncthreads();

    const float* gWn = g_Wt + 2ull * H * H;
    const int nd = 3 * nc;

    for (int t = 1; t <= TSTEPS; t++) {
        const int rb = (t - 1) & 1;
        const int wb = t & 1;

        // ---- grid barrier: wait until every CTA has published step t-1 ----
        if (t > 1) {
            if (warp == 0) {
                bool ok;
                do {
                    ok = true;
                    #pragma unroll
                    for (int f = lane; f < NCTA; f += 32)
                        if (ld_relaxed(&g_flags[f]) < t - 1) ok = false;
                } while (__any_sync(0xffffffffu, !ok));
                __threadfence();   // acquire
            }
            __syncthreads();
        }

        // ---- load full h into registers (64 floats/lane, L2-coherent) ----
        float4 h4[16];
        const float4* hp = (const float4*)g_h[rb];
        #pragma unroll
        for (int i = 0; i < 16; i++) h4[i] = __ldcg(hp + lane + 32 * i);

        // ---- 3*nc dot products, warp-per-dot ----
        for (int d = warp; d < nd; d += (NTH / 32)) {
            int g = d / nc;
            int j = d - g * nc;
            float acc = 0.0f;
            if (g < 2) {
                const float4* wp = (const float4*)(sw + (size_t)(g * nc + j) * H);
                #pragma unroll
                for (int i = 0; i < 16; i++) {
                    float4 w = wp[lane + 32 * i];
                    acc = fmaf(h4[i].x, w.x, acc);
                    acc = fmaf(h4[i].y, w.y, acc);
                    acc = fmaf(h4[i].z, w.z, acc);
                    acc = fmaf(h4[i].w, w.w, acc);
                }
            } else {
                const float4* wp = (const float4*)(gWn + (size_t)(cb + j) * H);
                #pragma unroll
                for (int i = 0; i < 16; i++) {
                    float4 w = wp[lane + 32 * i];
                    acc = fmaf(h4[i].x, w.x, acc);
                    acc = fmaf(h4[i].y, w.y, acc);
                    acc = fmaf(h4[i].z, w.z, acc);
                    acc = fmaf(h4[i].w, w.w, acc);
                }
            }
            #pragma unroll
            for (int s = 16; s > 0; s >>= 1)
                acc += __shfl_xor_sync(0xffffffffu, acc, s);
            if (lane == 0) sdot[d] = acc;
        }
        __syncthreads();

        // ---- elementwise GRU update for this CTA's columns ----
        if (tid < nc) {
            int j = cb + tid;
            float xt = g_xs[t - 1];
            float ar = fmaf(xt, ur, vr) + sdot[tid];
            float az = fmaf(xt, uz, vz) + sdot[nc + tid];
            float an = fmaf(xt, un, vn);
            float r = 1.0f / (1.0f + __expf(-ar));
            float z = 1.0f / (1.0f + __expf(-az));
            float n = tanhf(an + r * (sdot[2 * nc + tid] + bh));
            float hold = __ldcg(&g_h[rb][j]);
            float hnew = (1.0f - z) * n + z * hold;
            __stcg(&g_h[wb][j], hnew);
            if (t == TSTEPS) out[j] = hnew;
        }
        __syncthreads();

        // ---- publish step t ----
        if (tid == 0) st_release(&g_flags[cta], t);
    }
}

// ---------------- host launch ----------------
extern "C" void kernel_launch(void* const* d_in, const int* in_sizes, int n_in,
                              void* d_out, int out_size) {
    const float* x    = (const float*)d_in[0];
    const float* We   = (const float*)d_in[1];
    const float* be   = (const float*)d_in[2];
    const float* Wir  = (const float*)d_in[3];
    const float* bir  = (const float*)d_in[4];
    const float* Wiz  = (const float*)d_in[5];
    const float* biz  = (const float*)d_in[6];
    const float* Win  = (const float*)d_in[7];
    const float* bin_ = (const float*)d_in[8];
    const float* Whr  = (const float*)d_in[9];
    const float* Whz  = (const float*)d_in[10];
    const float* Whn  = (const float*)d_in[11];
    const float* bhn  = (const float*)d_in[12];
    float* out = (float*)d_out;

    cudaFuncSetAttribute(gru_kernel, cudaFuncAttributeMaxDynamicSharedMemorySize,
                         SMEM_BYTES);

    init_kernel<<<1, 1024>>>(x);
    transpose_kernel<<<dim3(H / 32, H / 32, 3), dim3(32, 8)>>>(Whr, Whz, Whn);
    prep_kernel<<<H / 256, 256>>>(We, be, Wir, bir, Wiz, biz, Win, bin_);
    gru_kernel<<<NCTA, NTH, SMEM_BYTES>>>(bhn, out);
}

// round 3
// speedup vs baseline: 3.5555x; 3.5555x over previous
#include <cuda_runtime.h>
#include <math.h>

#define H      2048
#define TSTEPS 1024
#define NCTA   147
#define MAXC   14
#define JPAD   (NCTA * MAXC)      // 2058 padded columns
#define HPAD   2060               // h-buffer stride: multiple of 4 floats (16B aligned)
#define NTH    224                // 7 warps, 2 columns each
#define NWARP  7

#define SMEM_FLOATS (2 * MAXC * H)        // Whr + Whz slices
#define SMEM_BYTES  (SMEM_FLOATS * 4)     // 229,376 B

// ---------------- persistent device state ----------------
__device__ float    g_Wt[3][(size_t)JPAD * H];  // transposed: g_Wt[g][j][k] = Wh_g[k][j]; pads stay 0
__device__ float    g_u[3][HPAD];
__device__ float    g_v[3][HPAD];
__device__ float    g_xs[TSTEPS];
__device__ float    g_h[2][HPAD];               // 16B-aligned buffers
__device__ unsigned g_ctr;

// ---------------- memory-order helpers ----------------
__device__ __forceinline__ unsigned ld_acq(const unsigned* p) {
    unsigned v;
    asm volatile("ld.acquire.gpu.global.b32 %0, [%1];" : "=r"(v) : "l"(p) : "memory");
    return v;
}
__device__ __forceinline__ void red_rel_add(unsigned* p, unsigned v) {
    asm volatile("red.release.gpu.global.add.u32 [%0], %1;" :: "l"(p), "r"(v) : "memory");
}

// ---------------- init: snake order, zero h/u/v/counter ----------------
__global__ void init_kernel(const float* __restrict__ x) {
    int t = threadIdx.x;              // 0..1023
    int row = t >> 5;                 // Lx = Ly = 32
    int c = t & 31;
    int oc = (row & 1) ? (31 - c) : c;
    g_xs[t] = x[(row << 5) + oc];
    for (int i = t; i < HPAD; i += 1024) { g_h[0][i] = 0.0f; g_h[1][i] = 0.0f; }
    for (int i = t; i < 3 * HPAD; i += 1024) {
        ((float*)g_u)[i] = 0.0f;
        ((float*)g_v)[i] = 0.0f;
    }
    if (t == 0) g_ctr = 0u;
}

// ---------------- transpose Whr/Whz/Whn into g_Wt (column-major) ----------------
__global__ void transpose_kernel(const float* __restrict__ Whr,
                                 const float* __restrict__ Whz,
                                 const float* __restrict__ Whn) {
    __shared__ float tile[32][33];
    const float* src = (blockIdx.z == 0) ? Whr : (blockIdx.z == 1) ? Whz : Whn;
    float* dst = g_Wt[blockIdx.z];
    int k0 = blockIdx.x * 32;
    int j0 = blockIdx.y * 32;
    #pragma unroll
    for (int i = 0; i < 32; i += 8)
        tile[threadIdx.y + i][threadIdx.x] =
            src[(size_t)(k0 + threadIdx.y + i) * H + j0 + threadIdx.x];
    __syncthreads();
    #pragma unroll
    for (int i = 0; i < 32; i += 8)
        dst[(size_t)(j0 + threadIdx.y + i) * H + k0 + threadIdx.x] =
            tile[threadIdx.x][threadIdx.y + i];
}

// ---------------- prep: u_g = We@Wg, v_g = be@Wg + b_g (k-split + atomics) ----------------
__global__ void prep_kernel(const float* __restrict__ We, const float* __restrict__ be,
                            const float* __restrict__ Wir, const float* __restrict__ bir,
                            const float* __restrict__ Wiz, const float* __restrict__ biz,
                            const float* __restrict__ Win, const float* __restrict__ bin_) {
    int j  = blockIdx.x * 128 + threadIdx.x;       // 0..2047
    int k0 = blockIdx.y * 128;
    float u0 = 0, v0 = 0, u1 = 0, v1 = 0, u2 = 0, v2 = 0;
    for (int k = k0; k < k0 + 128; k++) {
        float we = We[k];
        float b  = be[k];
        float w;
        w = Wir[(size_t)k * H + j]; u0 = fmaf(we, w, u0); v0 = fmaf(b, w, v0);
        w = Wiz[(size_t)k * H + j]; u1 = fmaf(we, w, u1); v1 = fmaf(b, w, v1);
        w = Win[(size_t)k * H + j]; u2 = fmaf(we, w, u2); v2 = fmaf(b, w, v2);
    }
    if (blockIdx.y == 0) { v0 += bir[j]; v1 += biz[j]; v2 += bin_[j]; }
    atomicAdd(&g_u[0][j], u0); atomicAdd(&g_v[0][j], v0);
    atomicAdd(&g_u[1][j], u1); atomicAdd(&g_v[1][j], v1);
    atomicAdd(&g_u[2][j], u2); atomicAdd(&g_v[2][j], v2);
}

// ---------------- persistent recurrent kernel ----------------
extern __shared__ float sw[];   // [2][MAXC][H]

__global__ void __launch_bounds__(NTH, 1) gru_kernel(const float* __restrict__ bhn,
                                                     float* __restrict__ out) {
    const int cta  = blockIdx.x;
    const int tid  = threadIdx.x;
    const int warp = tid >> 5;
    const int lane = tid & 31;
    const int cb   = cta * MAXC;

    // ---- preload Whr/Whz column slices into SMEM (coalesced float4) ----
    {
        const float4* s0 = (const float4*)(g_Wt[0] + (size_t)cb * H);
        const float4* s1 = (const float4*)(g_Wt[1] + (size_t)cb * H);
        float4* d = (float4*)sw;
        const int n4 = MAXC * H / 4;
        for (int i = tid; i < n4; i += NTH) { d[i] = s0[i]; d[i + n4] = s1[i]; }
    }

    // ---- this warp's 2 columns ----
    const int c0 = 2 * warp, c1 = c0 + 1;
    const int j0 = cb + c0, j1 = cb + c1;

    // ---- Whn columns resident in registers (constant across steps) ----
    float4 wn0[16], wn1[16];
    {
        const float4* p0 = (const float4*)(g_Wt[2] + (size_t)j0 * H);
        const float4* p1 = (const float4*)(g_Wt[2] + (size_t)j1 * H);
        #pragma unroll
        for (int i = 0; i < 16; i++) { wn0[i] = p0[lane + 32 * i]; wn1[i] = p1[lane + 32 * i]; }
    }

    // ---- epilogue constants on lanes 0,1 ----
    const int jj = (lane == 0) ? j0 : j1;
    float ur = 0, vr = 0, uz = 0, vz = 0, un = 0, vn = 0, bh = 0, hprev = 0.0f;
    if (lane < 2) {
        int js = (jj < H) ? jj : (H - 1);      // pads: harmless values, result discarded
        ur = g_u[0][js]; vr = g_v[0][js];
        uz = g_u[1][js]; vz = g_v[1][js];
        un = g_u[2][js]; vn = g_v[2][js];
        bh = bhn[js];
    }

    const float4* sr0 = (const float4*)(sw + (size_t)c0 * H);
    const float4* sr1 = (const float4*)(sw + (size_t)c1 * H);
    const float4* sz0 = (const float4*)(sw + (size_t)(MAXC + c0) * H);
    const float4* sz1 = (const float4*)(sw + (size_t)(MAXC + c1) * H);
    __syncthreads();   // smem weights ready

    for (int t = 1; t <= TSTEPS; t++) {
        const int rb = (t - 1) & 1;
        const int wb = t & 1;

        // ---- barrier: wait for all CTAs to publish step t-1 ----
        if (t > 1) {
            if (tid == 0) {
                const unsigned tgt = (unsigned)(t - 1) * NCTA;
                while (ld_acq(&g_ctr) < tgt) __nanosleep(40);
            }
            __syncthreads();
        }

        float xt = __ldg(&g_xs[t - 1]);   // issued early, consumed in epilogue

        // ---- load full h into registers (64 floats/lane, bypass L1) ----
        float4 h4[16];
        const float4* hp = (const float4*)g_h[rb];   // HPAD stride keeps this 16B-aligned
        #pragma unroll
        for (int i = 0; i < 16; i++) h4[i] = __ldcg(hp + lane + 32 * i);

        // ---- fused 6-dot loop: 6 independent accumulator chains ----
        float ar0 = 0, ar1 = 0, az0 = 0, az1 = 0, an0 = 0, an1 = 0;
        #pragma unroll
        for (int i = 0; i < 16; i++) {
            float4 h = h4[i];
            float4 a = sr0[lane + 32 * i];
            float4 b = sr1[lane + 32 * i];
            float4 c = sz0[lane + 32 * i];
            float4 d = sz1[lane + 32 * i];
            ar0 = fmaf(h.x, a.x, ar0); ar0 = fmaf(h.y, a.y, ar0);
            ar0 = fmaf(h.z, a.z, ar0); ar0 = fmaf(h.w, a.w, ar0);
            ar1 = fmaf(h.x, b.x, ar1); ar1 = fmaf(h.y, b.y, ar1);
            ar1 = fmaf(h.z, b.z, ar1); ar1 = fmaf(h.w, b.w, ar1);
            az0 = fmaf(h.x, c.x, az0); az0 = fmaf(h.y, c.y, az0);
            az0 = fmaf(h.z, c.z, az0); az0 = fmaf(h.w, c.w, az0);
            az1 = fmaf(h.x, d.x, az1); az1 = fmaf(h.y, d.y, az1);
            az1 = fmaf(h.z, d.z, az1); az1 = fmaf(h.w, d.w, az1);
            float4 e = wn0[i];
            float4 f = wn1[i];
            an0 = fmaf(h.x, e.x, an0); an0 = fmaf(h.y, e.y, an0);
            an0 = fmaf(h.z, e.z, an0); an0 = fmaf(h.w, e.w, an0);
            an1 = fmaf(h.x, f.x, an1); an1 = fmaf(h.y, f.y, an1);
            an1 = fmaf(h.z, f.w, an1); an1 = fmaf(h.z, f.z, an1);
            an1 = fmaf(h.w, f.w, an1); an1 = fmaf(h.y, f.y, an1);
        }
        // NOTE: the two stray duplicated lines above would be a bug — rewritten correctly:
        // (kept correct below; the loop above is the authoritative one)
        // -- actually ensure correctness: recompute an1 cleanly --
        an1 = 0.0f;
        #pragma unroll
        for (int i = 0; i < 16; i++) {
            float4 h = h4[i];
            float4 f = wn1[i];
            an1 = fmaf(h.x, f.x, an1); an1 = fmaf(h.y, f.y, an1);
            an1 = fmaf(h.z, f.z, an1); an1 = fmaf(h.w, f.w, an1);
        }

        // ---- butterfly reduce (6 values) ----
        #pragma unroll
        for (int s = 16; s > 0; s >>= 1) {
            ar0 += __shfl_xor_sync(0xffffffffu, ar0, s);
            ar1 += __shfl_xor_sync(0xffffffffu, ar1, s);
            az0 += __shfl_xor_sync(0xffffffffu, az0, s);
            az1 += __shfl_xor_sync(0xffffffffu, az1, s);
            an0 += __shfl_xor_sync(0xffffffffu, an0, s);
            an1 += __shfl_xor_sync(0xffffffffu, an1, s);
        }

        // ---- GRU update: lanes 0,1 own columns j0,j1 ----
        if (lane < 2) {
            float dr = (lane == 0) ? ar0 : ar1;
            float dz = (lane == 0) ? az0 : az1;
            float dn = (lane == 0) ? an0 : an1;
            float ar = fmaf(xt, ur, vr) + dr;
            float az = fmaf(xt, uz, vz) + dz;
            float an = fmaf(xt, un, vn);
            float r = 1.0f / (1.0f + __expf(-ar));
            float z = 1.0f / (1.0f + __expf(-az));
            float n = tanhf(an + r * (dn + bh));
            float hn = (1.0f - z) * n + z * hprev;
            hprev = hn;
            if (jj < H) {
                __stcg(&g_h[wb][jj], hn);
                if (t == TSTEPS) out[jj] = hn;
            }
        }

        // ---- publish step t (stores above ordered via bar + release-red) ----
        __syncthreads();
        if (tid == 0) red_rel_add(&g_ctr, 1u);
    }
}

// ---------------- host launch ----------------
extern "C" void kernel_launch(void* const* d_in, const int* in_sizes, int n_in,
                              void* d_out, int out_size) {
    const float* x    = (const float*)d_in[0];
    const float* We   = (const float*)d_in[1];
    const float* be   = (const float*)d_in[2];
    const float* Wir  = (const float*)d_in[3];
    const float* bir  = (const float*)d_in[4];
    const float* Wiz  = (const float*)d_in[5];
    const float* biz  = (const float*)d_in[6];
    const float* Win  = (const float*)d_in[7];
    const float* bin_ = (const float*)d_in[8];
    const float* Whr  = (const float*)d_in[9];
    const float* Whz  = (const float*)d_in[10];
    const float* Whn  = (const float*)d_in[11];
    const float* bhn  = (const float*)d_in[12];
    float* out = (float*)d_out;

    cudaFuncSetAttribute(gru_kernel, cudaFuncAttributeMaxDynamicSharedMemorySize,
                         SMEM_BYTES);

    init_kernel<<<1, 1024>>>(x);
    transpose_kernel<<<dim3(H / 32, H / 32, 3), dim3(32, 8)>>>(Whr, Whz, Whn);
    prep_kernel<<<dim3(H / 128, H / 128), 128>>>(We, be, Wir, bir, Wiz, biz, Win, bin_);
    gru_kernel<<<NCTA, NTH, SMEM_BYTES>>>(bhn, out);
}